// round 3
// baseline (speedup 1.0000x reference)
#include <cuda_runtime.h>
#include <math.h>
#include <stdint.h>

// Problem dims
constexpr int Bb = 128, Ss = 64, Ee = 256, Hh = 256, Dd = 256, Aa = 256, Vv = 10000;

// ---------------- scratch (single __device__ global; no allocation) -------
constexpr size_t OFF_EMB   = 0;
constexpr size_t OFF_XPF   = OFF_EMB   + (size_t)Bb*Ss*Ee;        // [B*S, 3H]
constexpr size_t OFF_XPB   = OFF_XPF   + (size_t)Bb*Ss*3*Hh;
constexpr size_t OFF_ENCO  = OFF_XPB   + (size_t)Bb*Ss*3*Hh;      // [B*S, 2H]
constexpr size_t OFF_ENCP  = OFF_ENCO  + (size_t)Bb*Ss*2*Hh;      // [B*S, A]
constexpr size_t OFF_HF0   = OFF_ENCP  + (size_t)Bb*Ss*Aa;
constexpr size_t OFF_HF1   = OFF_HF0   + (size_t)Bb*Hh;
constexpr size_t OFF_HB0   = OFF_HF1   + (size_t)Bb*Hh;
constexpr size_t OFF_HB1   = OFF_HB0   + (size_t)Bb*Hh;
constexpr size_t OFF_HID   = OFF_HB1   + (size_t)Bb*Hh;
constexpr size_t OFF_FCIN  = OFF_HID   + (size_t)Bb*Dd;
constexpr size_t OFF_HP1   = OFF_FCIN  + (size_t)Bb*2*Hh;         // dec hp
constexpr size_t OFF_HPROJ = OFF_HP1   + (size_t)Bb*3*Dd;
constexpr size_t OFF_RNIN  = OFF_HPROJ + (size_t)Bb*Aa;           // [B, E+2H]
constexpr size_t OFF_CAT   = OFF_RNIN  + (size_t)Bb*(Ee+2*Hh);    // [B, D+2H+E]
constexpr size_t OFF_SLOT  = OFF_CAT   + (size_t)Bb*(Dd+2*Hh+Ee); // 128 u64
constexpr size_t SCR_TOTAL = OFF_SLOT  + (size_t)2*Bb;

__device__ __align__(256) float g_scratch[SCR_TOTAL];

__device__ __forceinline__ float sigf(float x) { return 1.f / (1.f + expf(-x)); }

// monotonic float -> u32 mapping (preserves ordering, injective)
__device__ __forceinline__ unsigned int fmono(float x) {
    unsigned int b = __float_as_uint(x);
    return (b & 0x80000000u) ? ~b : (b | 0x80000000u);
}

// =====================================================================
//  gemmL: C[M,N] = A[M,K] @ B[N,K]^T (+bias)
//  BM=128, BN=64, BK=16, TM=8, TN=4, 256 threads, double-buffered smem.
//  Requires: M%128==0, K%16==0, lda%4==0, ldb%4==0, 16B-aligned A/B bases.
//  AMAX: fused per-row argmax into u64 slots (atomicMax).
// =====================================================================
template<int AMAX>
__global__ void gemmL(const float* __restrict__ A, int lda,
                      const float* __restrict__ Bm, int ldb,
                      float* __restrict__ C, int ldc,
                      const float* __restrict__ bias,
                      int M, int N, int K,
                      unsigned long long* __restrict__ slots)
{
    __shared__ __align__(16) float sA[2][16][132];
    __shared__ __align__(16) float sB[2][16][68];
    const int tid = threadIdx.x;
    const int tx = tid & 15, ty = tid >> 4;
    const int row0 = blockIdx.y * 128, col0 = blockIdx.x * 64;
    const int lr = tid >> 2;          // 0..63
    const int lc = (tid & 3) * 4;     // 0,4,8,12

    const float* Aptr0 = A + (size_t)(row0 + lr) * lda + lc;
    const float* Aptr1 = A + (size_t)(row0 + 64 + lr) * lda + lc;
    const int gnl = col0 + lr;
    const int gnc = (gnl < N) ? gnl : (N - 1);
    const float* Bptr = Bm + (size_t)gnc * ldb + lc;
    const bool bval = (gnl < N);

    float4 pa0 = *reinterpret_cast<const float4*>(Aptr0);
    float4 pa1 = *reinterpret_cast<const float4*>(Aptr1);
    float4 pb  = *reinterpret_cast<const float4*>(Bptr);
    if (!bval) pb = make_float4(0.f, 0.f, 0.f, 0.f);

    sA[0][lc+0][lr]    = pa0.x; sA[0][lc+1][lr]    = pa0.y;
    sA[0][lc+2][lr]    = pa0.z; sA[0][lc+3][lr]    = pa0.w;
    sA[0][lc+0][64+lr] = pa1.x; sA[0][lc+1][64+lr] = pa1.y;
    sA[0][lc+2][64+lr] = pa1.z; sA[0][lc+3][64+lr] = pa1.w;
    sB[0][lc+0][lr] = pb.x; sB[0][lc+1][lr] = pb.y;
    sB[0][lc+2][lr] = pb.z; sB[0][lc+3][lr] = pb.w;
    __syncthreads();

    float acc[8][4];
    #pragma unroll
    for (int i = 0; i < 8; i++)
        #pragma unroll
        for (int j = 0; j < 4; j++) acc[i][j] = 0.f;

    int buf = 0;
    for (int k0 = 16; k0 <= K; k0 += 16) {
        const bool has_next = (k0 < K);
        if (has_next) {
            pa0 = *reinterpret_cast<const float4*>(Aptr0 + k0);
            pa1 = *reinterpret_cast<const float4*>(Aptr1 + k0);
            pb  = *reinterpret_cast<const float4*>(Bptr + k0);
            if (!bval) pb = make_float4(0.f, 0.f, 0.f, 0.f);
        }
        #pragma unroll
        for (int kk = 0; kk < 16; kk++) {
            float4 av0 = *reinterpret_cast<const float4*>(&sA[buf][kk][ty*8]);
            float4 av1 = *reinterpret_cast<const float4*>(&sA[buf][kk][ty*8+4]);
            float4 bv  = *reinterpret_cast<const float4*>(&sB[buf][kk][tx*4]);
            float a[8] = {av0.x, av0.y, av0.z, av0.w, av1.x, av1.y, av1.z, av1.w};
            float b[4] = {bv.x, bv.y, bv.z, bv.w};
            #pragma unroll
            for (int i = 0; i < 8; i++)
                #pragma unroll
                for (int j = 0; j < 4; j++) acc[i][j] += a[i] * b[j];
        }
        if (has_next) {
            const int nb = buf ^ 1;
            sA[nb][lc+0][lr]    = pa0.x; sA[nb][lc+1][lr]    = pa0.y;
            sA[nb][lc+2][lr]    = pa0.z; sA[nb][lc+3][lr]    = pa0.w;
            sA[nb][lc+0][64+lr] = pa1.x; sA[nb][lc+1][64+lr] = pa1.y;
            sA[nb][lc+2][64+lr] = pa1.z; sA[nb][lc+3][64+lr] = pa1.w;
            sB[nb][lc+0][lr] = pb.x; sB[nb][lc+1][lr] = pb.y;
            sB[nb][lc+2][lr] = pb.z; sB[nb][lc+3][lr] = pb.w;
            __syncthreads();
            buf = nb;
        }
    }

    float bb[4];
    #pragma unroll
    for (int j = 0; j < 4; j++) {
        int gn = col0 + tx*4 + j;
        bb[j] = (bias && gn < N) ? bias[gn] : 0.f;
    }

    #pragma unroll
    for (int i = 0; i < 8; i++) {
        const int gm = row0 + ty*8 + i;
        float bestv = -INFINITY; int besti = 0;
        #pragma unroll
        for (int j = 0; j < 4; j++) {
            int gn = col0 + tx*4 + j;
            if (gn < N) {
                float v = acc[i][j] + bb[j];
                C[(size_t)gm * ldc + gn] = v;
                if (AMAX) { if (v > bestv) { bestv = v; besti = gn; } }
            }
        }
        if (AMAX) {
            unsigned long long key =
                ((unsigned long long)fmono(bestv) << 32) |
                (unsigned long long)(0xFFFFFFFFu - (unsigned)besti);
            #pragma unroll
            for (int o = 8; o; o >>= 1) {
                unsigned long long ok = __shfl_xor_sync(0xffffffffu, key, o);
                if (ok > key) key = ok;
            }
            if (tx == 0) atomicMax(&slots[gm], key);
        }
    }
}

// ---------------- generic small GEMM tile (device fn) ---------------------
template<int BM, int BN, int BK, int TM, int TN>
__device__ __forceinline__ void gemm_tile(const float* __restrict__ A, int lda,
                                          const float* __restrict__ Bm, int ldb,
                                          float* __restrict__ C, int ldc,
                                          const float* __restrict__ bias,
                                          int M, int N, int K,
                                          int row0, int col0, int ACT)
{
    constexpr int TX = BN / TN, TY = BM / TM;
    __shared__ float sA[BK][BM];
    __shared__ float sB[BK][BN];
    const int tid = threadIdx.x;
    const int tx = tid % TX, ty = tid / TX;

    float acc[TM][TN];
    #pragma unroll
    for (int i = 0; i < TM; i++)
        #pragma unroll
        for (int j = 0; j < TN; j++) acc[i][j] = 0.f;

    for (int k0 = 0; k0 < K; k0 += BK) {
        #pragma unroll
        for (int i = tid; i < BM * BK; i += TX * TY) {
            int m = i / BK, kk = i % BK;
            int gm = row0 + m;
            sA[kk][m] = (gm < M) ? A[(size_t)gm * lda + k0 + kk] : 0.f;
        }
        #pragma unroll
        for (int i = tid; i < BN * BK; i += TX * TY) {
            int n = i / BK, kk = i % BK;
            int gn = col0 + n;
            sB[kk][n] = (gn < N) ? Bm[(size_t)gn * ldb + k0 + kk] : 0.f;
        }
        __syncthreads();
        #pragma unroll
        for (int kk = 0; kk < BK; kk++) {
            float a[TM], b[TN];
            #pragma unroll
            for (int i = 0; i < TM; i++) a[i] = sA[kk][ty * TM + i];
            #pragma unroll
            for (int j = 0; j < TN; j++) b[j] = sB[kk][tx * TN + j];
            #pragma unroll
            for (int i = 0; i < TM; i++)
                #pragma unroll
                for (int j = 0; j < TN; j++) acc[i][j] += a[i] * b[j];
        }
        __syncthreads();
    }

    #pragma unroll
    for (int i = 0; i < TM; i++) {
        int gm = row0 + ty * TM + i;
        if (gm >= M) continue;
        #pragma unroll
        for (int j = 0; j < TN; j++) {
            int gn = col0 + tx * TN + j;
            if (gn >= N) continue;
            float v = acc[i][j] + (bias ? bias[gn] : 0.f);
            if (ACT == 1) v = tanhf(v);
            C[(size_t)gm * ldc + gn] = v;
        }
    }
}

template<int ACT>
__global__ void gemm32(const float* __restrict__ A, int lda,
                       const float* __restrict__ Bm, int ldb,
                       float* __restrict__ C, int ldc,
                       const float* __restrict__ bias,
                       int M, int N, int K)
{
    gemm_tile<32,32,32,2,2>(A, lda, Bm, ldb, C, ldc, bias, M, N, K,
                            blockIdx.y * 32, blockIdx.x * 32, ACT);
}

// Decoder: hproj = hid @ attn_W[:, :D]^T  AND  hp1 = hid @ dec_Whh^T + bhh
__global__ void dec_dual_gemm(const float* __restrict__ hid,
                              const float* __restrict__ attn_W,
                              const float* __restrict__ dec_Whh,
                              const float* __restrict__ dec_bhh,
                              float* __restrict__ hproj, float* __restrict__ hp1)
{
    int col0 = blockIdx.x * 32;
    if (col0 < Aa) {
        gemm_tile<32,32,32,2,2>(hid, Dd, attn_W, Dd + 2*Hh, hproj, Aa,
                                (const float*)nullptr, Bb, Aa, Dd,
                                blockIdx.y * 32, col0, 0);
    } else {
        gemm_tile<32,32,32,2,2>(hid, Dd, dec_Whh, Dd, hp1, 3*Dd,
                                dec_bhh, Bb, 3*Dd, Dd,
                                blockIdx.y * 32, col0 - Aa, 0);
    }
}

// =====================================================================
//  Encoder fused step: hp = h_in @ Whh^T + bhh (gate-strided columns)
//  then GRU gate; writes h_out and enc_out. grid (8 jblk, 4 bblk, 2 dir)
// =====================================================================
__global__ void enc_step_kernel(const float* __restrict__ hf_in,  const float* __restrict__ hb_in,
                                float* __restrict__ hf_out, float* __restrict__ hb_out,
                                const float* __restrict__ Whh_f, const float* __restrict__ Whh_b,
                                const float* __restrict__ bhh_f, const float* __restrict__ bhh_b,
                                const float* __restrict__ xpf,   const float* __restrict__ xpb,
                                float* __restrict__ enc_out, int t)
{
    const int dir = blockIdx.z;
    const float* hin  = dir ? hb_in  : hf_in;
    const float* Whh  = dir ? Whh_b  : Whh_f;
    const float* bhh  = dir ? bhh_b  : bhh_f;
    const float* xp   = dir ? xpb    : xpf;
    float*       hout = dir ? hb_out : hf_out;
    const int s = dir ? (Ss - 1 - t) : t;

    const int j0 = blockIdx.x * 32, b0 = blockIdx.y * 32;
    const int tid = threadIdx.x;
    const int tx = tid & 15, ty = tid >> 4;   // tx: j pairs, ty: b pairs

    __shared__ float sH[16][33];
    __shared__ float sW[3][16][34];

    float acc[2][2][3];
    #pragma unroll
    for (int bi = 0; bi < 2; bi++)
        #pragma unroll
        for (int ji = 0; ji < 2; ji++)
            #pragma unroll
            for (int g = 0; g < 3; g++) acc[bi][ji][g] = 0.f;

    for (int k0 = 0; k0 < Hh; k0 += 16) {
        #pragma unroll
        for (int i = tid; i < 512; i += 256) {
            int b = i >> 4, kk = i & 15;
            sH[kk][b] = hin[(size_t)(b0 + b) * Hh + k0 + kk];
        }
        #pragma unroll
        for (int i = tid; i < 1536; i += 256) {
            int r = i >> 4, kk = i & 15;
            int g = r / 32, j = r % 32;
            sW[g][kk][j] = Whh[(size_t)(g * Hh + j0 + j) * Hh + k0 + kk];
        }
        __syncthreads();
        #pragma unroll
        for (int kk = 0; kk < 16; kk++) {
            float hv[2] = { sH[kk][ty*2], sH[kk][ty*2 + 1] };
            #pragma unroll
            for (int g = 0; g < 3; g++) {
                float w0 = sW[g][kk][tx*2], w1 = sW[g][kk][tx*2 + 1];
                acc[0][0][g] += hv[0] * w0;
                acc[0][1][g] += hv[0] * w1;
                acc[1][0][g] += hv[1] * w0;
                acc[1][1][g] += hv[1] * w1;
            }
        }
        __syncthreads();
    }

    #pragma unroll
    for (int bi = 0; bi < 2; bi++) {
        int b = b0 + ty*2 + bi;
        #pragma unroll
        for (int ji = 0; ji < 2; ji++) {
            int j = j0 + tx*2 + ji;
            float rh = acc[bi][ji][0] + bhh[j];
            float zh = acc[bi][ji][1] + bhh[Hh + j];
            float nh = acc[bi][ji][2] + bhh[2*Hh + j];
            const float* x = xp + ((size_t)b * Ss + s) * (3*Hh);
            float r = sigf(x[j] + rh);
            float z = sigf(x[Hh + j] + zh);
            float n = tanhf(x[2*Hh + j] + r * nh);
            float hv = hin[(size_t)b * Hh + j];
            float hn = (1.f - z) * n + z * hv;
            hout[(size_t)b * Hh + j] = hn;
            enc_out[((size_t)b * Ss + s) * (2*Hh) + dir * Hh + j] = hn;
        }
    }
}

// =====================================================================
//  Decoder fused step: xp = rnin @ dec_Wih^T + bih (gate-strided cols),
//  then GRU gate with precomputed hp1; writes hid, cat, resets slots.
// =====================================================================
__global__ void dec_step_kernel(const float* __restrict__ rnin,
                                const float* __restrict__ dec_Wih,
                                const float* __restrict__ dec_bih,
                                const float* __restrict__ hp1,
                                float* __restrict__ hid, float* __restrict__ cat,
                                unsigned long long* __restrict__ slots)
{
    const int j0 = blockIdx.x * 32, b0 = blockIdx.y * 32;
    const int tid = threadIdx.x;
    const int tx = tid & 15, ty = tid >> 4;
    constexpr int Kk = Ee + 2*Hh;  // 768

    __shared__ float sH[16][33];
    __shared__ float sW[3][16][34];

    float acc[2][2][3];
    #pragma unroll
    for (int bi = 0; bi < 2; bi++)
        #pragma unroll
        for (int ji = 0; ji < 2; ji++)
            #pragma unroll
            for (int g = 0; g < 3; g++) acc[bi][ji][g] = 0.f;

    for (int k0 = 0; k0 < Kk; k0 += 16) {
        #pragma unroll
        for (int i = tid; i < 512; i += 256) {
            int b = i >> 4, kk = i & 15;
            sH[kk][b] = rnin[(size_t)(b0 + b) * Kk + k0 + kk];
        }
        #pragma unroll
        for (int i = tid; i < 1536; i += 256) {
            int r = i >> 4, kk = i & 15;
            int g = r / 32, j = r % 32;
            sW[g][kk][j] = dec_Wih[(size_t)(g * Dd + j0 + j) * Kk + k0 + kk];
        }
        __syncthreads();
        #pragma unroll
        for (int kk = 0; kk < 16; kk++) {
            float hv[2] = { sH[kk][ty*2], sH[kk][ty*2 + 1] };
            #pragma unroll
            for (int g = 0; g < 3; g++) {
                float w0 = sW[g][kk][tx*2], w1 = sW[g][kk][tx*2 + 1];
                acc[0][0][g] += hv[0] * w0;
                acc[0][1][g] += hv[0] * w1;
                acc[1][0][g] += hv[1] * w0;
                acc[1][1][g] += hv[1] * w1;
            }
        }
        __syncthreads();
    }

    #pragma unroll
    for (int bi = 0; bi < 2; bi++) {
        int b = b0 + ty*2 + bi;
        #pragma unroll
        for (int ji = 0; ji < 2; ji++) {
            int j = j0 + tx*2 + ji;
            float xr = acc[bi][ji][0] + dec_bih[j];
            float xz = acc[bi][ji][1] + dec_bih[Dd + j];
            float xn = acc[bi][ji][2] + dec_bih[2*Dd + j];
            const float* p = hp1 + (size_t)b * 3*Dd;
            float r = sigf(xr + p[j]);
            float z = sigf(xz + p[Dd + j]);
            float n = tanhf(xn + r * p[2*Dd + j]);
            float hv = hid[(size_t)b * Dd + j];
            float hn = (1.f - z) * n + z * hv;
            hid[(size_t)b * Dd + j] = hn;
            cat[(size_t)b * (Dd + 2*Hh + Ee) + j] = hn;
            if (j == 0) slots[b] = 0ull;
        }
    }
}

// ---------------- small helper kernels ------------------------------------
__global__ void init0_kernel(float* hf, float* hb, unsigned long long* slots)
{
    int i = blockIdx.x * 256 + threadIdx.x;
    if (i < Bb * Hh) { hf[i] = 0.f; hb[i] = 0.f; }
    if (i < Bb)
        slots[i] = ((unsigned long long)fmono(0.f) << 32) | 0xFFFFFFFFull; // idx 0
}

__global__ void embed_kernel(const int* __restrict__ inp,
                             const float* __restrict__ tab,
                             float* __restrict__ emb)
{
    int bs = blockIdx.x, j = threadIdx.x;
    int tk = inp[bs * 2 + 0];
    float m = (float)inp[bs * 2 + 1];
    emb[(size_t)bs * Ee + j] = tab[(size_t)tk * Ee + j] * m;
}

__global__ void concat_fc_kernel(const float* __restrict__ hf,
                                 const float* __restrict__ hb,
                                 float* __restrict__ fcin)
{
    int b = blockIdx.x, j = threadIdx.x;
    fcin[(size_t)b*2*Hh + j]      = hf[(size_t)b*Hh + j];
    fcin[(size_t)b*2*Hh + Hh + j] = hb[(size_t)b*Hh + j];
}

// attention + decoder-token embedding in one kernel
__global__ void attn_embed_kernel(const float* __restrict__ encp,
                                  const float* __restrict__ hproj,
                                  const float* __restrict__ enc_out,
                                  const unsigned long long* __restrict__ slots,
                                  const float* __restrict__ tab,
                                  float* __restrict__ rnin, float* __restrict__ cat)
{
    int b = blockIdx.x, tid = threadIdx.x;
    int lane = tid & 31, w = tid >> 5;
    __shared__ float shp[Aa];
    __shared__ float salpha[Ss];
    shp[tid] = hproj[(size_t)b*Aa + tid];
    __syncthreads();
    #pragma unroll
    for (int i = 0; i < 8; i++) {
        int s = w + 8 * i;
        const float* row = encp + ((size_t)b*Ss + s)*Aa;
        float acc = 0.f;
        #pragma unroll
        for (int a = lane; a < Aa; a += 32) acc += tanhf(row[a] + shp[a]);
        #pragma unroll
        for (int o = 16; o; o >>= 1) acc += __shfl_xor_sync(0xffffffffu, acc, o);
        if (lane == 0) salpha[s] = acc;
    }
    __syncthreads();
    if (w == 0) {
        float v0 = salpha[lane], v1 = salpha[lane + 32];
        float m = fmaxf(v0, v1);
        #pragma unroll
        for (int o = 16; o; o >>= 1) m = fmaxf(m, __shfl_xor_sync(0xffffffffu, m, o));
        float e0 = expf(v0 - m), e1 = expf(v1 - m);
        float sum = e0 + e1;
        #pragma unroll
        for (int o = 16; o; o >>= 1) sum += __shfl_xor_sync(0xffffffffu, sum, o);
        float inv = 1.f / sum;
        salpha[lane] = e0 * inv; salpha[lane + 32] = e1 * inv;
    }
    __syncthreads();
    float a0 = 0.f, a1 = 0.f;
    for (int s = 0; s < Ss; s++) {
        float al = salpha[s];
        const float* eo = enc_out + ((size_t)b*Ss + s)*(2*Hh);
        a0 += al * eo[tid];
        a1 += al * eo[Hh + tid];
    }
    rnin[(size_t)b*(Ee+2*Hh) + Ee + tid]      = a0;
    rnin[(size_t)b*(Ee+2*Hh) + Ee + Hh + tid] = a1;
    cat[(size_t)b*(Dd+2*Hh+Ee) + Dd + tid]      = a0;
    cat[(size_t)b*(Dd+2*Hh+Ee) + Dd + Hh + tid] = a1;

    // token embedding (decoded from packed argmax slot)
    int tk = (int)(0xFFFFFFFFu - (unsigned)(slots[b] & 0xFFFFFFFFull));
    float e = tab[(size_t)tk * Ee + tid];
    rnin[(size_t)b*(Ee+2*Hh) + tid] = e;
    cat[(size_t)b*(Dd+2*Hh+Ee) + Dd + 2*Hh + tid] = e;
}

__global__ void logsoftmax_kernel(float* __restrict__ out)
{
    int row = blockIdx.x, tid = threadIdx.x;
    int s = row & (Ss - 1);
    float* p = out + (size_t)row * Vv;
    if (s == 0) {
        float L = logf(expf(1.f) + (float)(Vv - 1));
        for (int v = tid; v < Vv; v += 256) p[v] = (v == 0 ? 1.f : 0.f) - L;
        return;
    }
    constexpr int PT = (Vv + 255) / 256;
    float regs[PT];
    float m = -INFINITY;
    #pragma unroll
    for (int i = 0; i < PT; i++) {
        int v = tid + i * 256;
        if (v < Vv) { regs[i] = p[v]; m = fmaxf(m, regs[i]); }
        else regs[i] = -INFINITY;
    }
    __shared__ float sm[256];
    sm[tid] = m; __syncthreads();
    for (int o = 128; o; o >>= 1) { if (tid < o) sm[tid] = fmaxf(sm[tid], sm[tid+o]); __syncthreads(); }
    m = sm[0]; __syncthreads();
    float sum = 0.f;
    #pragma unroll
    for (int i = 0; i < PT; i++) {
        int v = tid + i * 256;
        if (v < Vv) sum += expf(regs[i] - m);
    }
    sm[tid] = sum; __syncthreads();
    for (int o = 128; o; o >>= 1) { if (tid < o) sm[tid] += sm[tid+o]; __syncthreads(); }
    float ls = m + logf(sm[0]);
    #pragma unroll
    for (int i = 0; i < PT; i++) {
        int v = tid + i * 256;
        if (v < Vv) p[v] = regs[i] - ls;
    }
}

// ---------------- launch helpers ------------------------------------------
static inline dim3 gridL(int M, int N) { return dim3((N + 63) / 64, M / 128); }
static inline dim3 grid32(int M, int N) { return dim3((N + 31) / 32, (M + 31) / 32); }

extern "C" void kernel_launch(void* const* d_in, const int* in_sizes, int n_in,
                              void* d_out, int out_size)
{
    const int*   inp       = (const int*)  d_in[0];
    const float* emb_table = (const float*)d_in[1];
    const float* Wih_f     = (const float*)d_in[2];
    const float* Whh_f     = (const float*)d_in[3];
    const float* bih_f     = (const float*)d_in[4];
    const float* bhh_f     = (const float*)d_in[5];
    const float* Wih_b     = (const float*)d_in[6];
    const float* Whh_b     = (const float*)d_in[7];
    const float* bih_b     = (const float*)d_in[8];
    const float* bhh_b     = (const float*)d_in[9];
    const float* fc_W      = (const float*)d_in[10];
    const float* fc_b      = (const float*)d_in[11];
    const float* attn_W    = (const float*)d_in[12];
    const float* attn_b    = (const float*)d_in[13];
    const float* dec_Wih   = (const float*)d_in[14];
    const float* dec_Whh   = (const float*)d_in[15];
    const float* dec_bih   = (const float*)d_in[16];
    const float* dec_bhh   = (const float*)d_in[17];
    const float* out_W     = (const float*)d_in[18];
    const float* out_b     = (const float*)d_in[19];
    float* out = (float*)d_out;

    float* scr = nullptr;
    cudaGetSymbolAddress((void**)&scr, g_scratch);
    float* emb   = scr + OFF_EMB;
    float* xpf   = scr + OFF_XPF;
    float* xpb   = scr + OFF_XPB;
    float* enco  = scr + OFF_ENCO;
    float* encp  = scr + OFF_ENCP;
    float* hf0   = scr + OFF_HF0;
    float* hf1   = scr + OFF_HF1;
    float* hb0   = scr + OFF_HB0;
    float* hb1   = scr + OFF_HB1;
    float* hid   = scr + OFF_HID;
    float* fcin  = scr + OFF_FCIN;
    float* hp1   = scr + OFF_HP1;
    float* hproj = scr + OFF_HPROJ;
    float* rnin  = scr + OFF_RNIN;
    float* cat   = scr + OFF_CAT;
    unsigned long long* slots = (unsigned long long*)(scr + OFF_SLOT);

    // ---- init + embedding + one-time GEMMs ----
    init0_kernel<<<(Bb*Hh + 255)/256, 256>>>(hf0, hb0, slots);
    embed_kernel<<<Bb*Ss, 256>>>(inp, emb_table, emb);
    gemmL<0><<<gridL(Bb*Ss, 3*Hh), 256>>>(emb, Ee, Wih_f, Ee, xpf, 3*Hh, bih_f, Bb*Ss, 3*Hh, Ee, nullptr);
    gemmL<0><<<gridL(Bb*Ss, 3*Hh), 256>>>(emb, Ee, Wih_b, Ee, xpb, 3*Hh, bih_b, Bb*Ss, 3*Hh, Ee, nullptr);

    // ---- encoder recurrence (one fused launch per step, ping-pong h) ----
    for (int t = 0; t < Ss; t++) {
        const float* hfi = (t & 1) ? hf1 : hf0;
        const float* hbi = (t & 1) ? hb1 : hb0;
        float* hfo = (t & 1) ? hf0 : hf1;
        float* hbo = (t & 1) ? hb0 : hb1;
        enc_step_kernel<<<dim3(8, 4, 2), 256>>>(hfi, hbi, hfo, hbo,
                                                Whh_f, Whh_b, bhh_f, bhh_b,
                                                xpf, xpb, enco, t);
    }
    // Ss=64 even -> final hidden lives in hf0/hb0

    // ---- decoder init ----
    concat_fc_kernel<<<Bb, 256>>>(hf0, hb0, fcin);
    gemm32<1><<<grid32(Bb, Dd), 256>>>(fcin, 2*Hh, fc_W, 2*Hh, hid, Dd, fc_b, Bb, Dd, 2*Hh);

    // ---- precompute attention projection of enc_out ----
    gemmL<0><<<gridL(Bb*Ss, Aa), 256>>>(enco, 2*Hh, attn_W + Dd, Dd + 2*Hh, encp, Aa, attn_b, Bb*Ss, Aa, 2*Hh, nullptr);

    // ---- decoder steps (4 launches each) ----
    for (int t = 0; t < Ss - 1; t++) {
        dec_dual_gemm<<<dim3((Aa + 3*Dd)/32, Bb/32), 256>>>(hid, attn_W, dec_Whh, dec_bhh, hproj, hp1);
        attn_embed_kernel<<<Bb, 256>>>(encp, hproj, enco, slots, emb_table, rnin, cat);
        dec_step_kernel<<<dim3(8, 4), 256>>>(rnin, dec_Wih, dec_bih, hp1, hid, cat, slots);
        gemmL<1><<<gridL(Bb, Vv), 256>>>(cat, Dd + 2*Hh + Ee, out_W, Dd + 2*Hh + Ee,
                                         out + (size_t)(t + 1) * Vv, Ss * Vv, out_b,
                                         Bb, Vv, Dd + 2*Hh + Ee, slots);
    }

    // ---- final log-softmax ----
    logsoftmax_kernel<<<Bb*Ss, 256>>>(out);
}

// round 4
// speedup vs baseline: 1.0153x; 1.0153x over previous
#include <cuda_runtime.h>
#include <math.h>
#include <stdint.h>

// Problem dims
constexpr int Bb = 128, Ss = 64, Ee = 256, Hh = 256, Dd = 256, Aa = 256, Vv = 10000;
constexpr int CAT = Dd + 2*Hh + Ee;   // 1024
constexpr int RNK = Ee + 2*Hh;        // 768

// ---------------- scratch ---------------------------------------------------
constexpr size_t OFF_EMB   = 0;
constexpr size_t OFF_XPF   = OFF_EMB   + (size_t)Bb*Ss*Ee;
constexpr size_t OFF_XPB   = OFF_XPF   + (size_t)Bb*Ss*3*Hh;
constexpr size_t OFF_ENCO  = OFF_XPB   + (size_t)Bb*Ss*3*Hh;
constexpr size_t OFF_ENCP  = OFF_ENCO  + (size_t)Bb*Ss*2*Hh;
constexpr size_t OFF_HF0   = OFF_ENCP  + (size_t)Bb*Ss*Aa;
constexpr size_t OFF_HF1   = OFF_HF0   + (size_t)Bb*Hh;
constexpr size_t OFF_HB0   = OFF_HF1   + (size_t)Bb*Hh;
constexpr size_t OFF_HB1   = OFF_HB0   + (size_t)Bb*Hh;
constexpr size_t OFF_HID0  = OFF_HB1   + (size_t)Bb*Hh;
constexpr size_t OFF_HID1  = OFF_HID0  + (size_t)Bb*Dd;
constexpr size_t OFF_FCIN  = OFF_HID1  + (size_t)Bb*Dd;
constexpr size_t OFF_RNIN  = OFF_FCIN  + (size_t)Bb*2*Hh;
constexpr size_t OFF_CAT   = OFF_RNIN  + (size_t)Bb*RNK;
constexpr size_t OFF_ATTWT = OFF_CAT   + (size_t)Bb*CAT;      // [256][256] transposed
constexpr size_t OFF_SLOT  = OFF_ATTWT + (size_t)Dd*Aa;
constexpr size_t SCR_TOTAL = OFF_SLOT  + (size_t)2*Bb;

__device__ __align__(256) float g_scratch[SCR_TOTAL];

__device__ __forceinline__ float sigf(float x) { return 1.f / (1.f + expf(-x)); }

__device__ __forceinline__ unsigned int fmono(float x) {
    unsigned int b = __float_as_uint(x);
    return (b & 0x80000000u) ? ~b : (b | 0x80000000u);
}

// =====================================================================
//  gemmL: big one-time GEMMs. BM=128, BN=64, BK=16, TM=8, TN=4, 256 thr.
// =====================================================================
__global__ __launch_bounds__(256)
void gemmL(const float* __restrict__ A, int lda,
           const float* __restrict__ Bm, int ldb,
           float* __restrict__ C, int ldc,
           const float* __restrict__ bias,
           int M, int N, int K)
{
    __shared__ __align__(16) float sA[2][16][132];
    __shared__ __align__(16) float sB[2][16][68];
    const int tid = threadIdx.x;
    const int tx = tid & 15, ty = tid >> 4;
    const int row0 = blockIdx.y * 128, col0 = blockIdx.x * 64;
    const int lr = tid >> 2;
    const int lc = (tid & 3) * 4;

    const float* Aptr0 = A + (size_t)(row0 + lr) * lda + lc;
    const float* Aptr1 = A + (size_t)(row0 + 64 + lr) * lda + lc;
    const int gnl = col0 + lr;
    const int gnc = (gnl < N) ? gnl : (N - 1);
    const float* Bptr = Bm + (size_t)gnc * ldb + lc;
    const bool bval = (gnl < N);

    float4 pa0 = *reinterpret_cast<const float4*>(Aptr0);
    float4 pa1 = *reinterpret_cast<const float4*>(Aptr1);
    float4 pb  = *reinterpret_cast<const float4*>(Bptr);
    if (!bval) pb = make_float4(0.f, 0.f, 0.f, 0.f);

    sA[0][lc+0][lr]    = pa0.x; sA[0][lc+1][lr]    = pa0.y;
    sA[0][lc+2][lr]    = pa0.z; sA[0][lc+3][lr]    = pa0.w;
    sA[0][lc+0][64+lr] = pa1.x; sA[0][lc+1][64+lr] = pa1.y;
    sA[0][lc+2][64+lr] = pa1.z; sA[0][lc+3][64+lr] = pa1.w;
    sB[0][lc+0][lr] = pb.x; sB[0][lc+1][lr] = pb.y;
    sB[0][lc+2][lr] = pb.z; sB[0][lc+3][lr] = pb.w;
    __syncthreads();

    float acc[8][4];
    #pragma unroll
    for (int i = 0; i < 8; i++)
        #pragma unroll
        for (int j = 0; j < 4; j++) acc[i][j] = 0.f;

    int buf = 0;
    for (int k0 = 16; k0 <= K; k0 += 16) {
        const bool has_next = (k0 < K);
        if (has_next) {
            pa0 = *reinterpret_cast<const float4*>(Aptr0 + k0);
            pa1 = *reinterpret_cast<const float4*>(Aptr1 + k0);
            pb  = *reinterpret_cast<const float4*>(Bptr + k0);
            if (!bval) pb = make_float4(0.f, 0.f, 0.f, 0.f);
        }
        #pragma unroll
        for (int kk = 0; kk < 16; kk++) {
            float4 av0 = *reinterpret_cast<const float4*>(&sA[buf][kk][ty*8]);
            float4 av1 = *reinterpret_cast<const float4*>(&sA[buf][kk][ty*8+4]);
            float4 bv  = *reinterpret_cast<const float4*>(&sB[buf][kk][tx*4]);
            float a[8] = {av0.x, av0.y, av0.z, av0.w, av1.x, av1.y, av1.z, av1.w};
            float b[4] = {bv.x, bv.y, bv.z, bv.w};
            #pragma unroll
            for (int i = 0; i < 8; i++)
                #pragma unroll
                for (int j = 0; j < 4; j++) acc[i][j] += a[i] * b[j];
        }
        if (has_next) {
            const int nb = buf ^ 1;
            sA[nb][lc+0][lr]    = pa0.x; sA[nb][lc+1][lr]    = pa0.y;
            sA[nb][lc+2][lr]    = pa0.z; sA[nb][lc+3][lr]    = pa0.w;
            sA[nb][lc+0][64+lr] = pa1.x; sA[nb][lc+1][64+lr] = pa1.y;
            sA[nb][lc+2][64+lr] = pa1.z; sA[nb][lc+3][64+lr] = pa1.w;
            sB[nb][lc+0][lr] = pb.x; sB[nb][lc+1][lr] = pb.y;
            sB[nb][lc+2][lr] = pb.z; sB[nb][lc+3][lr] = pb.w;
            __syncthreads();
            buf = nb;
        }
    }

    #pragma unroll
    for (int i = 0; i < 8; i++) {
        const int gm = row0 + ty*8 + i;
        #pragma unroll
        for (int j = 0; j < 4; j++) {
            int gn = col0 + tx*4 + j;
            if (gn < N)
                C[(size_t)gm * ldc + gn] = acc[i][j] + (bias ? bias[gn] : 0.f);
        }
    }
}

// =====================================================================
//  gemmV: logits GEMM. BM=64, BN=64, BK=16, TM=8, TN=4, 128 threads,
//  double-buffered. Fused per-row argmax into slots.
//  Requires M%64==0, K%16==0, lda%4==0, ldb%4==0.
// =====================================================================
__global__ __launch_bounds__(128)
void gemmV(const float* __restrict__ A, int lda,
           const float* __restrict__ Bm, int ldb,
           float* __restrict__ C, int ldc,
           const float* __restrict__ bias,
           int M, int N, int K,
           unsigned long long* __restrict__ slots)
{
    __shared__ __align__(16) float sA[2][16][68];
    __shared__ __align__(16) float sB[2][16][68];
    const int tid = threadIdx.x;
    const int tx = tid & 15, ty = tid >> 4;   // 16 x 8
    const int row0 = blockIdx.y * 64, col0 = blockIdx.x * 64;
    const int lr = tid >> 1;                  // 0..63
    const int lc = (tid & 1) * 8;             // 0 or 8

    const float* Aptr = A + (size_t)(row0 + lr) * lda + lc;
    const int gnl = col0 + lr;
    const int gnc = (gnl < N) ? gnl : (N - 1);
    const float* Bptr = Bm + (size_t)gnc * ldb + lc;
    const bool bval = (gnl < N);

    float4 pa0 = *reinterpret_cast<const float4*>(Aptr);
    float4 pa1 = *reinterpret_cast<const float4*>(Aptr + 4);
    float4 pb0 = *reinterpret_cast<const float4*>(Bptr);
    float4 pb1 = *reinterpret_cast<const float4*>(Bptr + 4);
    if (!bval) { pb0 = make_float4(0,0,0,0); pb1 = make_float4(0,0,0,0); }

    sA[0][lc+0][lr] = pa0.x; sA[0][lc+1][lr] = pa0.y;
    sA[0][lc+2][lr] = pa0.z; sA[0][lc+3][lr] = pa0.w;
    sA[0][lc+4][lr] = pa1.x; sA[0][lc+5][lr] = pa1.y;
    sA[0][lc+6][lr] = pa1.z; sA[0][lc+7][lr] = pa1.w;
    sB[0][lc+0][lr] = pb0.x; sB[0][lc+1][lr] = pb0.y;
    sB[0][lc+2][lr] = pb0.z; sB[0][lc+3][lr] = pb0.w;
    sB[0][lc+4][lr] = pb1.x; sB[0][lc+5][lr] = pb1.y;
    sB[0][lc+6][lr] = pb1.z; sB[0][lc+7][lr] = pb1.w;
    __syncthreads();

    float acc[8][4];
    #pragma unroll
    for (int i = 0; i < 8; i++)
        #pragma unroll
        for (int j = 0; j < 4; j++) acc[i][j] = 0.f;

    int buf = 0;
    for (int k0 = 16; k0 <= K; k0 += 16) {
        const bool has_next = (k0 < K);
        if (has_next) {
            pa0 = *reinterpret_cast<const float4*>(Aptr + k0);
            pa1 = *reinterpret_cast<const float4*>(Aptr + k0 + 4);
            pb0 = *reinterpret_cast<const float4*>(Bptr + k0);
            pb1 = *reinterpret_cast<const float4*>(Bptr + k0 + 4);
            if (!bval) { pb0 = make_float4(0,0,0,0); pb1 = make_float4(0,0,0,0); }
        }
        #pragma unroll
        for (int kk = 0; kk < 16; kk++) {
            float4 av0 = *reinterpret_cast<const float4*>(&sA[buf][kk][ty*8]);
            float4 av1 = *reinterpret_cast<const float4*>(&sA[buf][kk][ty*8+4]);
            float4 bv  = *reinterpret_cast<const float4*>(&sB[buf][kk][tx*4]);
            float a[8] = {av0.x, av0.y, av0.z, av0.w, av1.x, av1.y, av1.z, av1.w};
            float b[4] = {bv.x, bv.y, bv.z, bv.w};
            #pragma unroll
            for (int i = 0; i < 8; i++)
                #pragma unroll
                for (int j = 0; j < 4; j++) acc[i][j] += a[i] * b[j];
        }
        if (has_next) {
            const int nb = buf ^ 1;
            sA[nb][lc+0][lr] = pa0.x; sA[nb][lc+1][lr] = pa0.y;
            sA[nb][lc+2][lr] = pa0.z; sA[nb][lc+3][lr] = pa0.w;
            sA[nb][lc+4][lr] = pa1.x; sA[nb][lc+5][lr] = pa1.y;
            sA[nb][lc+6][lr] = pa1.z; sA[nb][lc+7][lr] = pa1.w;
            sB[nb][lc+0][lr] = pb0.x; sB[nb][lc+1][lr] = pb0.y;
            sB[nb][lc+2][lr] = pb0.z; sB[nb][lc+3][lr] = pb0.w;
            sB[nb][lc+4][lr] = pb1.x; sB[nb][lc+5][lr] = pb1.y;
            sB[nb][lc+6][lr] = pb1.z; sB[nb][lc+7][lr] = pb1.w;
            __syncthreads();
            buf = nb;
        }
    }

    float bb[4];
    #pragma unroll
    for (int j = 0; j < 4; j++) {
        int gn = col0 + tx*4 + j;
        bb[j] = (bias && gn < N) ? bias[gn] : 0.f;
    }

    #pragma unroll
    for (int i = 0; i < 8; i++) {
        const int gm = row0 + ty*8 + i;
        float bestv = -INFINITY; int besti = 0;
        #pragma unroll
        for (int j = 0; j < 4; j++) {
            int gn = col0 + tx*4 + j;
            if (gn < N) {
                float v = acc[i][j] + bb[j];
                C[(size_t)gm * ldc + gn] = v;
                if (v > bestv) { bestv = v; besti = gn; }
            }
        }
        unsigned long long key =
            ((unsigned long long)fmono(bestv) << 32) |
            (unsigned long long)(0xFFFFFFFFu - (unsigned)besti);
        #pragma unroll
        for (int o = 8; o; o >>= 1) {
            unsigned long long ok = __shfl_xor_sync(0xffffffffu, key, o);
            if (ok > key) key = ok;
        }
        if (tx == 0) atomicMax(&slots[gm], key);
    }
}

// ---------------- small generic GEMM (decoder init only) -------------------
__global__ void gemm32t(const float* __restrict__ A, int lda,
                        const float* __restrict__ Bm, int ldb,
                        float* __restrict__ C, int ldc,
                        const float* __restrict__ bias,
                        int M, int N, int K)
{
    __shared__ float sA[32][33];
    __shared__ float sB[32][33];
    const int tid = threadIdx.x;
    const int tx = tid & 15, ty = tid >> 4;
    const int row0 = blockIdx.y * 32, col0 = blockIdx.x * 32;

    float acc[2][2] = {{0,0},{0,0}};
    for (int k0 = 0; k0 < K; k0 += 32) {
        #pragma unroll
        for (int i = tid; i < 1024; i += 256) {
            int m = i >> 5, kk = i & 31;
            sA[kk][m] = A[(size_t)(row0 + m) * lda + k0 + kk];
            sB[kk][m] = Bm[(size_t)(col0 + m) * ldb + k0 + kk];
        }
        __syncthreads();
        #pragma unroll
        for (int kk = 0; kk < 32; kk++) {
            float a0 = sA[kk][ty*2], a1 = sA[kk][ty*2+1];
            float b0 = sB[kk][tx*2], b1 = sB[kk][tx*2+1];
            acc[0][0] += a0*b0; acc[0][1] += a0*b1;
            acc[1][0] += a1*b0; acc[1][1] += a1*b1;
        }
        __syncthreads();
    }
    #pragma unroll
    for (int i = 0; i < 2; i++)
        #pragma unroll
        for (int j = 0; j < 2; j++) {
            int gm = row0 + ty*2 + i, gn = col0 + tx*2 + j;
            C[(size_t)gm * ldc + gn] = tanhf(acc[i][j] + bias[gn]);
        }
}

// =====================================================================
//  Encoder fused step (unchanged from round 3)
// =====================================================================
__global__ __launch_bounds__(256)
void enc_step_kernel(const float* __restrict__ hf_in,  const float* __restrict__ hb_in,
                     float* __restrict__ hf_out, float* __restrict__ hb_out,
                     const float* __restrict__ Whh_f, const float* __restrict__ Whh_b,
                     const float* __restrict__ bhh_f, const float* __restrict__ bhh_b,
                     const float* __restrict__ xpf,   const float* __restrict__ xpb,
                     float* __restrict__ enc_out, int t)
{
    const int dir = blockIdx.z;
    const float* hin  = dir ? hb_in  : hf_in;
    const float* Whh  = dir ? Whh_b  : Whh_f;
    const float* bhh  = dir ? bhh_b  : bhh_f;
    const float* xp   = dir ? xpb    : xpf;
    float*       hout = dir ? hb_out : hf_out;
    const int s = dir ? (Ss - 1 - t) : t;

    const int j0 = blockIdx.x * 32, b0 = blockIdx.y * 32;
    const int tid = threadIdx.x;
    const int tx = tid & 15, ty = tid >> 4;

    __shared__ float sH[16][33];
    __shared__ float sW[3][16][34];

    float acc[2][2][3];
    #pragma unroll
    for (int bi = 0; bi < 2; bi++)
        #pragma unroll
        for (int ji = 0; ji < 2; ji++)
            #pragma unroll
            for (int g = 0; g < 3; g++) acc[bi][ji][g] = 0.f;

    for (int k0 = 0; k0 < Hh; k0 += 16) {
        #pragma unroll
        for (int i = tid; i < 512; i += 256) {
            int b = i >> 4, kk = i & 15;
            sH[kk][b] = hin[(size_t)(b0 + b) * Hh + k0 + kk];
        }
        #pragma unroll
        for (int i = tid; i < 1536; i += 256) {
            int r = i >> 4, kk = i & 15;
            int g = r / 32, j = r % 32;
            sW[g][kk][j] = Whh[(size_t)(g * Hh + j0 + j) * Hh + k0 + kk];
        }
        __syncthreads();
        #pragma unroll
        for (int kk = 0; kk < 16; kk++) {
            float hv[2] = { sH[kk][ty*2], sH[kk][ty*2 + 1] };
            #pragma unroll
            for (int g = 0; g < 3; g++) {
                float w0 = sW[g][kk][tx*2], w1 = sW[g][kk][tx*2 + 1];
                acc[0][0][g] += hv[0] * w0;
                acc[0][1][g] += hv[0] * w1;
                acc[1][0][g] += hv[1] * w0;
                acc[1][1][g] += hv[1] * w1;
            }
        }
        __syncthreads();
    }

    #pragma unroll
    for (int bi = 0; bi < 2; bi++) {
        int b = b0 + ty*2 + bi;
        #pragma unroll
        for (int ji = 0; ji < 2; ji++) {
            int j = j0 + tx*2 + ji;
            float rh = acc[bi][ji][0] + bhh[j];
            float zh = acc[bi][ji][1] + bhh[Hh + j];
            float nh = acc[bi][ji][2] + bhh[2*Hh + j];
            const float* x = xp + ((size_t)b * Ss + s) * (3*Hh);
            float r = sigf(x[j] + rh);
            float z = sigf(x[Hh + j] + zh);
            float n = tanhf(x[2*Hh + j] + r * nh);
            float hv = hin[(size_t)b * Hh + j];
            float hn = (1.f - z) * n + z * hv;
            hout[(size_t)b * Hh + j] = hn;
            enc_out[((size_t)b * Ss + s) * (2*Hh) + dir * Hh + j] = hn;
        }
    }
}

// =====================================================================
//  Decoder fused GRU step: r/z over concat K=1024, nx (K=768) + nh (K=256)
//  grid (8 jblk, 4 bblk), 256 threads.
// =====================================================================
__global__ __launch_bounds__(256)
void dec_fused_kernel(const float* __restrict__ rnin,
                      const float* __restrict__ hid_in,
                      const float* __restrict__ dec_Wih,
                      const float* __restrict__ dec_Whh,
                      const float* __restrict__ dec_bih,
                      const float* __restrict__ dec_bhh,
                      float* __restrict__ hid_out, float* __restrict__ cat,
                      unsigned long long* __restrict__ slots)
{
    const int j0 = blockIdx.x * 32, b0 = blockIdx.y * 32;
    const int tid = threadIdx.x;
    const int tx = tid & 15, ty = tid >> 4;

    __shared__ float sH[16][33];
    __shared__ float sW[4][16][34];   // g: 0=r,1=z,2=nx,3=nh

    float acc[2][2][4];
    #pragma unroll
    for (int bi = 0; bi < 2; bi++)
        #pragma unroll
        for (int ji = 0; ji < 2; ji++)
            #pragma unroll
            for (int g = 0; g < 4; g++) acc[bi][ji][g] = 0.f;

    for (int k0 = 0; k0 < RNK + Dd; k0 += 16) {   // 1024
        const bool ih = (k0 < RNK);
        #pragma unroll
        for (int i = tid; i < 512; i += 256) {
            int b = i >> 4, kk = i & 15;
            sH[kk][b] = ih ? rnin[(size_t)(b0 + b) * RNK + k0 + kk]
                           : hid_in[(size_t)(b0 + b) * Dd + (k0 - RNK) + kk];
        }
        #pragma unroll
        for (int i = tid; i < 2048; i += 256) {
            int g = i >> 9;
            int r = (i >> 4) & 31;
            int kk = i & 15;
            int j = j0 + r;
            float w;
            if (ih) {
                w = (g == 3) ? 0.f
                    : dec_Wih[(size_t)(g * Dd + j) * RNK + k0 + kk];
            } else {
                w = (g == 2) ? 0.f
                    : dec_Whh[(size_t)(((g == 3) ? 2 : g) * Dd + j) * Dd + (k0 - RNK) + kk];
            }
            sW[g][kk][r] = w;
        }
        __syncthreads();
        #pragma unroll
        for (int kk = 0; kk < 16; kk++) {
            float hv0 = sH[kk][ty*2], hv1 = sH[kk][ty*2 + 1];
            #pragma unroll
            for (int g = 0; g < 4; g++) {
                float w0 = sW[g][kk][tx*2], w1 = sW[g][kk][tx*2 + 1];
                acc[0][0][g] += hv0 * w0;
                acc[0][1][g] += hv0 * w1;
                acc[1][0][g] += hv1 * w0;
                acc[1][1][g] += hv1 * w1;
            }
        }
        __syncthreads();
    }

    #pragma unroll
    for (int bi = 0; bi < 2; bi++) {
        int b = b0 + ty*2 + bi;
        #pragma unroll
        for (int ji = 0; ji < 2; ji++) {
            int j = j0 + tx*2 + ji;
            float r = sigf(acc[bi][ji][0] + dec_bih[j] + dec_bhh[j]);
            float z = sigf(acc[bi][ji][1] + dec_bih[Dd + j] + dec_bhh[Dd + j]);
            float n = tanhf(acc[bi][ji][2] + dec_bih[2*Dd + j]
                            + r * (acc[bi][ji][3] + dec_bhh[2*Dd + j]));
            float hv = hid_in[(size_t)b * Dd + j];
            float hn = (1.f - z) * n + z * hv;
            hid_out[(size_t)b * Dd + j] = hn;
            cat[(size_t)b * CAT + j] = hn;
            if (j == 0) slots[b] = 0ull;
        }
    }
}

// ---------------- small helper kernels ------------------------------------
__global__ void init0_kernel(float* hf, float* hb, unsigned long long* slots)
{
    int i = blockIdx.x * 256 + threadIdx.x;
    if (i < Bb * Hh) { hf[i] = 0.f; hb[i] = 0.f; }
    if (i < Bb)
        slots[i] = ((unsigned long long)fmono(0.f) << 32) | 0xFFFFFFFFull;
}

__global__ void embed_kernel(const int* __restrict__ inp,
                             const float* __restrict__ tab,
                             float* __restrict__ emb)
{
    int bs = blockIdx.x, j = threadIdx.x;
    int tk = inp[bs * 2 + 0];
    float m = (float)inp[bs * 2 + 1];
    emb[(size_t)bs * Ee + j] = tab[(size_t)tk * Ee + j] * m;
}

// one-time: transpose attn_W[:, :Dd] into attWT[k][j]
__global__ void transpose_attw_kernel(const float* __restrict__ attn_W,
                                      float* __restrict__ attWT)
{
    int k = blockIdx.x, j = threadIdx.x;
    attWT[(size_t)k * Aa + j] = attn_W[(size_t)j * (Dd + 2*Hh) + k];
}

__global__ void concat_fc_kernel(const float* __restrict__ hf,
                                 const float* __restrict__ hb,
                                 float* __restrict__ fcin)
{
    int b = blockIdx.x, j = threadIdx.x;
    fcin[(size_t)b*2*Hh + j]      = hf[(size_t)b*Hh + j];
    fcin[(size_t)b*2*Hh + Hh + j] = hb[(size_t)b*Hh + j];
}

// attention (with fused hproj) + decoder-token embedding
__global__ __launch_bounds__(256)
void attn_embed_kernel(const float* __restrict__ encp,
                       const float* __restrict__ hid,
                       const float* __restrict__ attWT,
                       const float* __restrict__ enc_out,
                       const unsigned long long* __restrict__ slots,
                       const float* __restrict__ tab,
                       float* __restrict__ rnin, float* __restrict__ cat)
{
    int b = blockIdx.x, tid = threadIdx.x;
    int lane = tid & 31, w = tid >> 5;
    __shared__ float shid[Dd];
    __shared__ float shp[Aa];
    __shared__ float salpha[Ss];

    shid[tid] = hid[(size_t)b*Dd + tid];
    __syncthreads();

    // hproj[j] = sum_k hid[k] * attWT[k][j]   (coalesced, L2-resident)
    float hp = 0.f;
    #pragma unroll 8
    for (int k = 0; k < Dd; k++) hp += shid[k] * attWT[(size_t)k * Aa + tid];
    shp[tid] = hp;
    __syncthreads();

    #pragma unroll
    for (int i = 0; i < 8; i++) {
        int s = w + 8 * i;
        const float* row = encp + ((size_t)b*Ss + s)*Aa;
        float acc = 0.f;
        #pragma unroll
        for (int a = lane; a < Aa; a += 32) acc += tanhf(row[a] + shp[a]);
        #pragma unroll
        for (int o = 16; o; o >>= 1) acc += __shfl_xor_sync(0xffffffffu, acc, o);
        if (lane == 0) salpha[s] = acc;
    }
    __syncthreads();
    if (w == 0) {
        float v0 = salpha[lane], v1 = salpha[lane + 32];
        float m = fmaxf(v0, v1);
        #pragma unroll
        for (int o = 16; o; o >>= 1) m = fmaxf(m, __shfl_xor_sync(0xffffffffu, m, o));
        float e0 = expf(v0 - m), e1 = expf(v1 - m);
        float sum = e0 + e1;
        #pragma unroll
        for (int o = 16; o; o >>= 1) sum += __shfl_xor_sync(0xffffffffu, sum, o);
        float inv = 1.f / sum;
        salpha[lane] = e0 * inv; salpha[lane + 32] = e1 * inv;
    }
    __syncthreads();
    float a0 = 0.f, a1 = 0.f;
    for (int s = 0; s < Ss; s++) {
        float al = salpha[s];
        const float* eo = enc_out + ((size_t)b*Ss + s)*(2*Hh);
        a0 += al * eo[tid];
        a1 += al * eo[Hh + tid];
    }
    rnin[(size_t)b*RNK + Ee + tid]      = a0;
    rnin[(size_t)b*RNK + Ee + Hh + tid] = a1;
    cat[(size_t)b*CAT + Dd + tid]       = a0;
    cat[(size_t)b*CAT + Dd + Hh + tid]  = a1;

    int tk = (int)(0xFFFFFFFFu - (unsigned)(slots[b] & 0xFFFFFFFFull));
    float e = tab[(size_t)tk * Ee + tid];
    rnin[(size_t)b*RNK + tid] = e;
    cat[(size_t)b*CAT + Dd + 2*Hh + tid] = e;
}

__global__ void logsoftmax_kernel(float* __restrict__ out)
{
    int row = blockIdx.x, tid = threadIdx.x;
    int s = row & (Ss - 1);
    float* p = out + (size_t)row * Vv;
    if (s == 0) {
        float L = logf(expf(1.f) + (float)(Vv - 1));
        for (int v = tid; v < Vv; v += 256) p[v] = (v == 0 ? 1.f : 0.f) - L;
        return;
    }
    constexpr int PT = (Vv + 255) / 256;
    float regs[PT];
    float m = -INFINITY;
    #pragma unroll
    for (int i = 0; i < PT; i++) {
        int v = tid + i * 256;
        if (v < Vv) { regs[i] = p[v]; m = fmaxf(m, regs[i]); }
        else regs[i] = -INFINITY;
    }
    __shared__ float sm[256];
    sm[tid] = m; __syncthreads();
    for (int o = 128; o; o >>= 1) { if (tid < o) sm[tid] = fmaxf(sm[tid], sm[tid+o]); __syncthreads(); }
    m = sm[0]; __syncthreads();
    float sum = 0.f;
    #pragma unroll
    for (int i = 0; i < PT; i++) {
        int v = tid + i * 256;
        if (v < Vv) sum += expf(regs[i] - m);
    }
    sm[tid] = sum; __syncthreads();
    for (int o = 128; o; o >>= 1) { if (tid < o) sm[tid] += sm[tid+o]; __syncthreads(); }
    float ls = m + logf(sm[0]);
    #pragma unroll
    for (int i = 0; i < PT; i++) {
        int v = tid + i * 256;
        if (v < Vv) p[v] = regs[i] - ls;
    }
}

// ---------------- launch helpers ------------------------------------------
static inline dim3 gridL(int M, int N) { return dim3((N + 63) / 64, M / 128); }
static inline dim3 gridV(int M, int N) { return dim3((N + 63) / 64, M / 64); }

extern "C" void kernel_launch(void* const* d_in, const int* in_sizes, int n_in,
                              void* d_out, int out_size)
{
    const int*   inp       = (const int*)  d_in[0];
    const float* emb_table = (const float*)d_in[1];
    const float* Wih_f     = (const float*)d_in[2];
    const float* Whh_f     = (const float*)d_in[3];
    const float* bih_f     = (const float*)d_in[4];
    const float* bhh_f     = (const float*)d_in[5];
    const float* Wih_b     = (const float*)d_in[6];
    const float* Whh_b     = (const float*)d_in[7];
    const float* bih_b     = (const float*)d_in[8];
    const float* bhh_b     = (const float*)d_in[9];
    const float* fc_W      = (const float*)d_in[10];
    const float* fc_b      = (const float*)d_in[11];
    const float* attn_W    = (const float*)d_in[12];
    const float* attn_b    = (const float*)d_in[13];
    const float* dec_Wih   = (const float*)d_in[14];
    const float* dec_Whh   = (const float*)d_in[15];
    const float* dec_bih   = (const float*)d_in[16];
    const float* dec_bhh   = (const float*)d_in[17];
    const float* out_W     = (const float*)d_in[18];
    const float* out_b     = (const float*)d_in[19];
    float* out = (float*)d_out;

    float* scr = nullptr;
    cudaGetSymbolAddress((void**)&scr, g_scratch);
    float* emb   = scr + OFF_EMB;
    float* xpf   = scr + OFF_XPF;
    float* xpb   = scr + OFF_XPB;
    float* enco  = scr + OFF_ENCO;
    float* encp  = scr + OFF_ENCP;
    float* hf0   = scr + OFF_HF0;
    float* hf1   = scr + OFF_HF1;
    float* hb0   = scr + OFF_HB0;
    float* hb1   = scr + OFF_HB1;
    float* hid0  = scr + OFF_HID0;
    float* hid1  = scr + OFF_HID1;
    float* fcin  = scr + OFF_FCIN;
    float* rnin  = scr + OFF_RNIN;
    float* cat   = scr + OFF_CAT;
    float* attWT = scr + OFF_ATTWT;
    unsigned long long* slots = (unsigned long long*)(scr + OFF_SLOT);

    // ---- init + embedding + one-time GEMMs ----
    init0_kernel<<<(Bb*Hh + 255)/256, 256>>>(hf0, hb0, slots);
    embed_kernel<<<Bb*Ss, 256>>>(inp, emb_table, emb);
    transpose_attw_kernel<<<Dd, Aa>>>(attn_W, attWT);
    gemmL<<<gridL(Bb*Ss, 3*Hh), 256>>>(emb, Ee, Wih_f, Ee, xpf, 3*Hh, bih_f, Bb*Ss, 3*Hh, Ee);
    gemmL<<<gridL(Bb*Ss, 3*Hh), 256>>>(emb, Ee, Wih_b, Ee, xpb, 3*Hh, bih_b, Bb*Ss, 3*Hh, Ee);

    // ---- encoder recurrence ----
    for (int t = 0; t < Ss; t++) {
        const float* hfi = (t & 1) ? hf1 : hf0;
        const float* hbi = (t & 1) ? hb1 : hb0;
        float* hfo = (t & 1) ? hf0 : hf1;
        float* hbo = (t & 1) ? hb0 : hb1;
        enc_step_kernel<<<dim3(8, 4, 2), 256>>>(hfi, hbi, hfo, hbo,
                                                Whh_f, Whh_b, bhh_f, bhh_b,
                                                xpf, xpb, enco, t);
    }

    // ---- decoder init ----
    concat_fc_kernel<<<Bb, 256>>>(hf0, hb0, fcin);
    gemm32t<<<dim3(Dd/32, Bb/32), 256>>>(fcin, 2*Hh, fc_W, 2*Hh, hid0, Dd, fc_b, Bb, Dd, 2*Hh);

    // ---- attention projection of enc_out (one-time) ----
    gemmL<<<gridL(Bb*Ss, Aa), 256>>>(enco, 2*Hh, attn_W + Dd, Dd + 2*Hh, encp, Aa, attn_b, Bb*Ss, Aa, 2*Hh);

    // ---- decoder steps (3 launches each) ----
    for (int t = 0; t < Ss - 1; t++) {
        const float* hin = (t & 1) ? hid1 : hid0;
        float*       hout = (t & 1) ? hid0 : hid1;
        attn_embed_kernel<<<Bb, 256>>>(encp, hin, attWT, enco, slots, emb_table, rnin, cat);
        dec_fused_kernel<<<dim3(8, 4), 256>>>(rnin, hin, dec_Wih, dec_Whh,
                                              dec_bih, dec_bhh, hout, cat, slots);
        gemmV<<<gridV(Bb, Vv), 128>>>(cat, CAT, out_W, CAT,
                                      out + (size_t)(t + 1) * Vv, Ss * Vv, out_b,
                                      Bb, Vv, CAT, slots);
    }

    // ---- final log-softmax ----
    logsoftmax_kernel<<<Bb*Ss, 256>>>(out);
}